// round 15
// baseline (speedup 1.0000x reference)
#include <cuda_runtime.h>
#include <cuda_bf16.h>
#include <cuda_fp16.h>
#include <math.h>

// ---------------- problem constants ----------------
#define N_NODES 100000
#define N_EDGES 3200000
#define IN_F    500
#define HID     64
#define OUT_F   64
#define ALPHA   0.1f
#define K_ITERS 10

#define NSCAN_BLOCKS ((N_NODES + 1023) / 1024)   // 98
#define SCALE_S 0.0625                            // 1/16 per-iteration z scaling
#define WQ_SCALE 32767.0f
#define WQ_INV   (1.0f / 32767.0f)

typedef unsigned long long u64;

// ---------------- static device scratch ----------------
__device__ __half   g_hh[N_NODES * OUT_F];        // fp16 h (= y_0, alpha term)
__device__ __half   g_ya[N_NODES * OUT_F];        // fp16 iterate ping
__device__ __half   g_yb[N_NODES * OUT_F];        // fp16 iterate pong
__device__ int      g_deg[N_NODES];               // ALWAYS zero at launch entry
__device__ int      g_off[N_NODES + 1];
__device__ int      g_pos[N_NODES];
__device__ unsigned g_epk[N_EDGES];               // packed edge: w15 | src17
__device__ int      g_bsum[NSCAN_BLOCKS];

// ---------------- CSR construction (4 kernels) ----------------
__global__ void hist_kernel(const int* __restrict__ dst) {
    int i = blockIdx.x * blockDim.x + threadIdx.x;
    if (i * 4 + 3 < N_EDGES) {
        int4 d = ((const int4*)dst)[i];
        atomicAdd(&g_deg[d.x], 1);
        atomicAdd(&g_deg[d.y], 1);
        atomicAdd(&g_deg[d.z], 1);
        atomicAdd(&g_deg[d.w], 1);
    } else {
        for (int e = i * 4; e < N_EDGES; e++) atomicAdd(&g_deg[dst[e]], 1);
    }
}

__global__ void scan_local_kernel() {
    __shared__ int s[1024];
    int tid = threadIdx.x;
    int i = blockIdx.x * 1024 + tid;
    int v = (i < N_NODES) ? g_deg[i] : 0;
    s[tid] = v;
    __syncthreads();
    #pragma unroll
    for (int d = 1; d < 1024; d <<= 1) {
        int t = (tid >= d) ? s[tid - d] : 0;
        __syncthreads();
        s[tid] += t;
        __syncthreads();
    }
    if (i < N_NODES) {
        g_off[i] = s[tid] - v;     // exclusive local
        g_deg[i] = 0;              // restore zero invariant for next launch
    }
    if (tid == 1023) g_bsum[blockIdx.x] = s[1023];
}

__global__ void scan_add_kernel() {
    __shared__ int red[32];
    int tid  = threadIdx.x;
    int lane = tid & 31;
    int wid  = tid >> 5;
    int pre = 0;
    for (int t = tid; t < blockIdx.x; t += 1024) pre += g_bsum[t];
    #pragma unroll
    for (int d = 16; d; d >>= 1) pre += __shfl_down_sync(0xffffffffu, pre, d);
    if (lane == 0) red[wid] = pre;
    __syncthreads();
    if (wid == 0) {
        int v = red[lane];
        #pragma unroll
        for (int d = 16; d; d >>= 1) v += __shfl_down_sync(0xffffffffu, v, d);
        if (lane == 0) red[0] = v;
    }
    __syncthreads();
    int base = red[0];

    int i = blockIdx.x * 1024 + tid;
    if (i < N_NODES) {
        int o = g_off[i] + base;
        g_off[i] = o;
        g_pos[i] = o;
    }
    if (blockIdx.x == 0 && tid == 0) g_off[N_NODES] = N_EDGES;
}

// 4 edges per thread, vectorized int4 loads of src/dst/w.
__global__ void scatter_kernel(const int* __restrict__ src,
                               const int* __restrict__ dst,
                               const float* __restrict__ w) {
    int i = blockIdx.x * blockDim.x + threadIdx.x;
    if (i * 4 + 3 < N_EDGES) {
        int4 d = ((const int4*)dst)[i];
        int4 s = ((const int4*)src)[i];
        float4 wv = ((const float4*)w)[i];
        int p0 = atomicAdd(&g_pos[d.x], 1);
        int p1 = atomicAdd(&g_pos[d.y], 1);
        int p2 = atomicAdd(&g_pos[d.z], 1);
        int p3 = atomicAdd(&g_pos[d.w], 1);
        g_epk[p0] = (((unsigned)__float2int_rn(wv.x * WQ_SCALE)) << 17) | (unsigned)s.x;
        g_epk[p1] = (((unsigned)__float2int_rn(wv.y * WQ_SCALE)) << 17) | (unsigned)s.y;
        g_epk[p2] = (((unsigned)__float2int_rn(wv.z * WQ_SCALE)) << 17) | (unsigned)s.z;
        g_epk[p3] = (((unsigned)__float2int_rn(wv.w * WQ_SCALE)) << 17) | (unsigned)s.w;
    } else {
        for (int e = i * 4; e < N_EDGES; e++) {
            int d = dst[e];
            int p = atomicAdd(&g_pos[d], 1);
            unsigned q = (unsigned)__float2int_rn(w[e] * WQ_SCALE);
            g_epk[p] = (q << 17) | (unsigned)src[e];
        }
    }
}

// ---------------- fused MLP on tensor cores ----------------
// h = relu(x@W1+b1)@W2 + b2, bf16 hi/lo split (3 MMA passes), fp32 acc.
// Writes ONLY fp16 h (g_hh) — final prop iteration also uses fp16 h.
#define S1_STRIDE 40
#define S2_STRIDE 72
#define OFF_WREG  18432
#define SMEM_MLP_USHORT (18432 + 9216)
#define SMEM_MLP_BYTES  (SMEM_MLP_USHORT * 2)   // 55296 B

#define MMA_BF16(d, a, b0_, b1_)                                              \
    asm volatile("mma.sync.aligned.m16n8k16.row.col.f32.bf16.bf16.f32 "       \
                 "{%0,%1,%2,%3}, {%4,%5,%6,%7}, {%8,%9}, {%0,%1,%2,%3};"      \
                 : "+f"(d[0]), "+f"(d[1]), "+f"(d[2]), "+f"(d[3])             \
                 : "r"(a[0]), "r"(a[1]), "r"(a[2]), "r"(a[3]),                \
                   "r"(b0_), "r"(b1_))

__device__ __forceinline__ void bf16_split(float v, unsigned short& h,
                                           unsigned short& l) {
    __nv_bfloat16 hb = __float2bfloat16(v);
    float hf = __bfloat162float(hb);
    __nv_bfloat16 lb = __float2bfloat16(v - hf);
    h = __bfloat16_as_ushort(hb);
    l = __bfloat16_as_ushort(lb);
}

__global__ __launch_bounds__(256)
void mlp_tc_kernel(const float* __restrict__ A,
                   const float* __restrict__ W1, const float* __restrict__ b1,
                   const float* __restrict__ W2, const float* __restrict__ b2,
                   __half* __restrict__ Hh, int nrows) {
    extern __shared__ unsigned short sm[];
    unsigned short* xs_hi = sm;                         // 128*40
    unsigned short* xs_lo = sm + 128 * S1_STRIDE;
    unsigned short* wt_hi = sm + OFF_WREG;              // 64*40
    unsigned short* wt_lo = sm + OFF_WREG + 64 * S1_STRIDE;
    unsigned short* h1_hi = sm;                         // 128*72 (alias)
    unsigned short* h1_lo = sm + 128 * S2_STRIDE;
    unsigned short* w2_hi = sm + OFF_WREG;              // 64*72 (alias)
    unsigned short* w2_lo = sm + OFF_WREG + 64 * S2_STRIDE;

    const int tid  = threadIdx.x;
    const int wid  = tid >> 5;
    const int lane = tid & 31;
    const int g    = lane >> 2;
    const int tg2  = (lane & 3) * 2;
    const int warp_m = wid & 3;
    const int warp_n = wid >> 2;
    const int row0 = blockIdx.x * 128;

    float acc[2][4][4];
    #pragma unroll
    for (int mt = 0; mt < 2; mt++)
        #pragma unroll
        for (int nt = 0; nt < 4; nt++)
            #pragma unroll
            for (int c = 0; c < 4; c++) acc[mt][nt][c] = 0.f;

    // ================= stage 1: h1 = x @ W1 =================
    for (int ko = 0; ko < IN_F; ko += 32) {
        #pragma unroll
        for (int i = 0; i < 16; i++) {
            int idx = tid + i * 256;
            int r = idx >> 5;
            int c = idx & 31;
            int gr = row0 + r;
            int gk = ko + c;
            float v = (gr < nrows && gk < IN_F) ? __ldg(&A[(long)gr * IN_F + gk]) : 0.f;
            unsigned short hv, lv;
            bf16_split(v, hv, lv);
            xs_hi[r * S1_STRIDE + c] = hv;
            xs_lo[r * S1_STRIDE + c] = lv;
        }
        #pragma unroll
        for (int i = 0; i < 8; i++) {
            int idx = tid + i * 256;
            int k = idx >> 6;
            int n = idx & 63;
            int gk = ko + k;
            float v = (gk < IN_F) ? W1[gk * 64 + n] : 0.f;
            unsigned short hv, lv;
            bf16_split(v, hv, lv);
            wt_hi[n * S1_STRIDE + k] = hv;
            wt_lo[n * S1_STRIDE + k] = lv;
        }
        __syncthreads();

        #pragma unroll
        for (int ks = 0; ks < 2; ks++) {
            const int kk = ks * 16;
            unsigned ahi[2][4], alo[2][4];
            #pragma unroll
            for (int mt = 0; mt < 2; mt++) {
                int br = warp_m * 32 + mt * 16;
                const unsigned short* ph = &xs_hi[(br + g) * S1_STRIDE + kk + tg2];
                const unsigned short* pl = &xs_lo[(br + g) * S1_STRIDE + kk + tg2];
                ahi[mt][0] = *(const unsigned*)(ph);
                ahi[mt][1] = *(const unsigned*)(ph + 8 * S1_STRIDE);
                ahi[mt][2] = *(const unsigned*)(ph + 8);
                ahi[mt][3] = *(const unsigned*)(ph + 8 * S1_STRIDE + 8);
                alo[mt][0] = *(const unsigned*)(pl);
                alo[mt][1] = *(const unsigned*)(pl + 8 * S1_STRIDE);
                alo[mt][2] = *(const unsigned*)(pl + 8);
                alo[mt][3] = *(const unsigned*)(pl + 8 * S1_STRIDE + 8);
            }
            #pragma unroll
            for (int nt = 0; nt < 4; nt++) {
                int bn = warp_n * 32 + nt * 8 + g;
                const unsigned short* qh = &wt_hi[bn * S1_STRIDE + kk + tg2];
                const unsigned short* ql = &wt_lo[bn * S1_STRIDE + kk + tg2];
                unsigned bh0 = *(const unsigned*)(qh);
                unsigned bh1 = *(const unsigned*)(qh + 8);
                unsigned bl0 = *(const unsigned*)(ql);
                unsigned bl1 = *(const unsigned*)(ql + 8);
                #pragma unroll
                for (int mt = 0; mt < 2; mt++) {
                    MMA_BF16(acc[mt][nt], ahi[mt], bh0, bh1);
                    MMA_BF16(acc[mt][nt], ahi[mt], bl0, bl1);
                    MMA_BF16(acc[mt][nt], alo[mt], bh0, bh1);
                }
            }
        }
        __syncthreads();
    }

    // ============ inter-stage: bias1 + relu, h1 -> smem (bf16 hi/lo) ========
    #pragma unroll
    for (int mt = 0; mt < 2; mt++) {
        int r0 = warp_m * 32 + mt * 16 + g;
        int r1 = r0 + 8;
        #pragma unroll
        for (int nt = 0; nt < 4; nt++) {
            int col = warp_n * 32 + nt * 8 + tg2;
            float bb0 = b1[col], bb1 = b1[col + 1];
            float v0 = fmaxf(acc[mt][nt][0] + bb0, 0.f);
            float v1 = fmaxf(acc[mt][nt][1] + bb1, 0.f);
            float v2 = fmaxf(acc[mt][nt][2] + bb0, 0.f);
            float v3 = fmaxf(acc[mt][nt][3] + bb1, 0.f);
            unsigned short h0, l0, h1v, l1, h2, l2, h3, l3;
            bf16_split(v0, h0, l0); bf16_split(v1, h1v, l1);
            bf16_split(v2, h2, l2); bf16_split(v3, h3, l3);
            *(unsigned*)&h1_hi[r0 * S2_STRIDE + col] = (unsigned)h0 | ((unsigned)h1v << 16);
            *(unsigned*)&h1_lo[r0 * S2_STRIDE + col] = (unsigned)l0 | ((unsigned)l1 << 16);
            *(unsigned*)&h1_hi[r1 * S2_STRIDE + col] = (unsigned)h2 | ((unsigned)h3 << 16);
            *(unsigned*)&h1_lo[r1 * S2_STRIDE + col] = (unsigned)l2 | ((unsigned)l3 << 16);
            acc[mt][nt][0] = 0.f; acc[mt][nt][1] = 0.f;
            acc[mt][nt][2] = 0.f; acc[mt][nt][3] = 0.f;
        }
    }
    #pragma unroll
    for (int i = 0; i < 16; i++) {
        int idx = tid + i * 256;
        int k = idx >> 6;
        int n = idx & 63;
        float v = W2[k * 64 + n];
        unsigned short hv, lv;
        bf16_split(v, hv, lv);
        w2_hi[n * S2_STRIDE + k] = hv;
        w2_lo[n * S2_STRIDE + k] = lv;
    }
    __syncthreads();

    // ================= stage 2: h = h1 @ W2 (K=64) =================
    #pragma unroll
    for (int ks = 0; ks < 4; ks++) {
        const int kk = ks * 16;
        unsigned ahi[2][4], alo[2][4];
        #pragma unroll
        for (int mt = 0; mt < 2; mt++) {
            int br = warp_m * 32 + mt * 16;
            const unsigned short* ph = &h1_hi[(br + g) * S2_STRIDE + kk + tg2];
            const unsigned short* pl = &h1_lo[(br + g) * S2_STRIDE + kk + tg2];
            ahi[mt][0] = *(const unsigned*)(ph);
            ahi[mt][1] = *(const unsigned*)(ph + 8 * S2_STRIDE);
            ahi[mt][2] = *(const unsigned*)(ph + 8);
            ahi[mt][3] = *(const unsigned*)(ph + 8 * S2_STRIDE + 8);
            alo[mt][0] = *(const unsigned*)(pl);
            alo[mt][1] = *(const unsigned*)(pl + 8 * S2_STRIDE);
            alo[mt][2] = *(const unsigned*)(pl + 8);
            alo[mt][3] = *(const unsigned*)(pl + 8 * S2_STRIDE + 8);
        }
        #pragma unroll
        for (int nt = 0; nt < 4; nt++) {
            int bn = warp_n * 32 + nt * 8 + g;
            const unsigned short* qh = &w2_hi[bn * S2_STRIDE + kk + tg2];
            const unsigned short* ql = &w2_lo[bn * S2_STRIDE + kk + tg2];
            unsigned bh0 = *(const unsigned*)(qh);
            unsigned bh1 = *(const unsigned*)(qh + 8);
            unsigned bl0 = *(const unsigned*)(ql);
            unsigned bl1 = *(const unsigned*)(ql + 8);
            #pragma unroll
            for (int mt = 0; mt < 2; mt++) {
                MMA_BF16(acc[mt][nt], ahi[mt], bh0, bh1);
                MMA_BF16(acc[mt][nt], ahi[mt], bl0, bl1);
                MMA_BF16(acc[mt][nt], alo[mt], bh0, bh1);
            }
        }
    }

    // ============ epilogue: bias2, write fp16 h only ============
    #pragma unroll
    for (int mt = 0; mt < 2; mt++) {
        int r0 = row0 + warp_m * 32 + mt * 16 + g;
        int r1 = r0 + 8;
        #pragma unroll
        for (int nt = 0; nt < 4; nt++) {
            int col = warp_n * 32 + nt * 8 + tg2;
            float bb0 = b2[col], bb1 = b2[col + 1];
            if (r0 < nrows) {
                __half2 p = __floats2half2_rn(acc[mt][nt][0] + bb0,
                                              acc[mt][nt][1] + bb1);
                *(unsigned*)&Hh[(long)r0 * 64 + col] = *(unsigned*)&p;
            }
            if (r1 < nrows) {
                __half2 p = __floats2half2_rn(acc[mt][nt][2] + bb0,
                                              acc[mt][nt][3] + bb1);
                *(unsigned*)&Hh[(long)r1 * 64 + col] = *(unsigned*)&p;
            }
        }
    }
}

// ---------------- APPNP propagation (half-warp per edge, balanced tail) ----
#define PAIR_BODY(PJ) {                                                       \
    float wj = (float)((PJ) >> 17) * WQ_INV;                                  \
    uint2 v = *(const uint2*)(yin + ((long)((PJ) & 0x1FFFFu) << 6) + (hl << 2)); \
    float2 f0 = __half22float2(*(__half2*)&v.x);                              \
    float2 f1 = __half22float2(*(__half2*)&v.y);                              \
    a0 = fmaf(wj, f0.x, a0); a1 = fmaf(wj, f0.y, a1);                         \
    a2 = fmaf(wj, f1.x, a2); a3 = fmaf(wj, f1.y, a3); }

template <bool FINAL>
__global__ __launch_bounds__(256)
void prop_kernel(const __half* __restrict__ yin,
                 const uint2* __restrict__ hh,
                 uint2* __restrict__ yout, float4* __restrict__ fout,
                 float c1, float c2) {
    int gtid = blockIdx.x * blockDim.x + threadIdx.x;
    int node = gtid >> 5;
    int lane = threadIdx.x & 31;
    if (node >= N_NODES) return;
    const int hl = lane & 15;

    int beg = g_off[node];
    int end = g_off[node + 1];

    float a0 = 0.f, a1 = 0.f, a2 = 0.f, a3 = 0.f;
    int e = beg;
    for (; e + 32 <= end; e += 32) {
        unsigned pe = __ldg(&g_epk[e + lane]);
        #pragma unroll
        for (int j = 0; j < 16; j++) {
            unsigned pj = __shfl_sync(0xffffffffu, pe, j, 16);
            PAIR_BODY(pj)
        }
    }
    if (e < end) {
        int idx = e + lane;
        unsigned pe = (idx < end) ? __ldg(&g_epk[idx]) : 0u;
        int cnt  = end - e;                 // 1..31
        int jcnt = (cnt + 1) >> 1;
        int hoff = (lane & 16) ? jcnt : 0;
        for (int j = 0; j < jcnt; j++) {
            unsigned pj = __shfl_sync(0xffffffffu, pe, j + hoff, 32);
            PAIR_BODY(pj)
        }
    }
    a0 += __shfl_xor_sync(0xffffffffu, a0, 16);
    a1 += __shfl_xor_sync(0xffffffffu, a1, 16);
    a2 += __shfl_xor_sync(0xffffffffu, a2, 16);
    a3 += __shfl_xor_sync(0xffffffffu, a3, 16);

    if (lane < 16) {
        long oi = (long)node * 16 + hl;
        uint2 hv2 = hh[oi];
        float2 f0 = __half22float2(*(__half2*)&hv2.x);
        float2 f1 = __half22float2(*(__half2*)&hv2.y);
        float r0 = fmaf(c1, a0, c2 * f0.x);
        float r1 = fmaf(c1, a1, c2 * f0.y);
        float r2 = fmaf(c1, a2, c2 * f1.x);
        float r3 = fmaf(c1, a3, c2 * f1.y);
        if (FINAL) {
            fout[oi] = make_float4(r0, r1, r2, r3);
        } else {
            __half2 p0 = __floats2half2_rn(r0, r1);
            __half2 p1 = __floats2half2_rn(r2, r3);
            uint2 pv; pv.x = *(unsigned*)&p0; pv.y = *(unsigned*)&p1;
            yout[oi] = pv;
        }
    }
}

// ---------------- launch ----------------
extern "C" void kernel_launch(void* const* d_in, const int* in_sizes, int n_in,
                              void* d_out, int out_size) {
    const float* x    = (const float*)d_in[0];
    const int*   esrc = (const int*)d_in[1];
    const int*   edst = (const int*)d_in[2];
    const float* ew   = (const float*)d_in[3];
    const float* W1   = (const float*)d_in[4];
    const float* b1   = (const float*)d_in[5];
    const float* W2   = (const float*)d_in[6];
    const float* b2   = (const float*)d_in[7];
    float* out = (float*)d_out;

    static cudaStream_t s_side = nullptr;
    static cudaEvent_t  s_evFork = nullptr, s_evJoin = nullptr;
    if (!s_side) {
        cudaStreamCreateWithFlags(&s_side, cudaStreamNonBlocking);
        cudaEventCreateWithFlags(&s_evFork, cudaEventDisableTiming);
        cudaEventCreateWithFlags(&s_evJoin, cudaEventDisableTiming);
        cudaFuncSetAttribute(mlp_tc_kernel,
                             cudaFuncAttributeMaxDynamicSharedMemorySize,
                             SMEM_MLP_BYTES);
    }

    __half *hh_p, *ya_p, *yb_p;
    cudaGetSymbolAddress((void**)&hh_p, g_hh);
    cudaGetSymbolAddress((void**)&ya_p, g_ya);
    cudaGetSymbolAddress((void**)&yb_p, g_yb);

    // --- fork: CSR build on side stream, concurrent with fused MLP ---
    cudaEventRecord(s_evFork, 0);
    cudaStreamWaitEvent(s_side, s_evFork, 0);
    hist_kernel<<<(N_EDGES / 4 + 255) / 256, 256, 0, s_side>>>(edst);
    scan_local_kernel<<<NSCAN_BLOCKS, 1024, 0, s_side>>>();
    scan_add_kernel<<<NSCAN_BLOCKS, 1024, 0, s_side>>>();
    scatter_kernel<<<(N_EDGES / 4 + 255) / 256, 256, 0, s_side>>>(esrc, edst, ew);
    cudaEventRecord(s_evJoin, s_side);

    // --- fused MLP on main stream (writes fp16 h) ---
    int gblocks = (N_NODES + 127) / 128;
    mlp_tc_kernel<<<gblocks, 256, SMEM_MLP_BYTES>>>(x, W1, b1, W2, b2,
                                                    hh_p, N_NODES);

    // --- join, then K propagation steps ---
    cudaStreamWaitEvent(0, s_evJoin, 0);

    int pblocks = (N_NODES * 32 + 255) / 256;
    const __half* yin = hh_p;                 // y_0 = fp16(h)
    __half* ybufs[2] = { ya_p, yb_p };
    for (int k = 0; k < K_ITERS; k++) {
        if (k < K_ITERS - 1) {
            float c1 = (float)(0.9 * SCALE_S);
            float c2 = (float)(0.1 * pow(SCALE_S, (double)(k + 1)));
            __half* yo = ybufs[k & 1];
            prop_kernel<false><<<pblocks, 256>>>(yin, (const uint2*)hh_p,
                                                 (uint2*)yo, nullptr, c1, c2);
            yin = yo;
        } else {
            float c1 = (float)(0.9 * pow(1.0 / SCALE_S, (double)(K_ITERS - 1)));
            float c2 = 0.1f;
            prop_kernel<true><<<pblocks, 256>>>(yin, (const uint2*)hh_p,
                                                nullptr, (float4*)out, c1, c2);
        }
    }
}

// round 16
// speedup vs baseline: 1.0139x; 1.0139x over previous
#include <cuda_runtime.h>
#include <cuda_bf16.h>
#include <cuda_fp16.h>
#include <math.h>

// ---------------- problem constants ----------------
#define N_NODES 100000
#define N_EDGES 3200000
#define IN_F    500
#define HID     64
#define OUT_F   64
#define ALPHA   0.1f
#define K_ITERS 10

#define NSCAN_BLOCKS ((N_NODES + 1023) / 1024)   // 98
#define SCALE_S 0.0625                            // 1/16 per-iteration z scaling
#define WQ_SCALE 32767.0f
#define WQ_INV   (1.0f / 32767.0f)

typedef unsigned long long u64;

// ---------------- static device scratch ----------------
__device__ __half   g_hh[N_NODES * OUT_F];        // fp16 h (= y_0, alpha term)
__device__ __half   g_ya[N_NODES * OUT_F];        // fp16 iterate ping
__device__ __half   g_yb[N_NODES * OUT_F];        // fp16 iterate pong
__device__ int      g_deg[N_NODES];               // ALWAYS zero at launch entry
__device__ int      g_off[N_NODES + 1];
__device__ int      g_pos[N_NODES];
__device__ unsigned g_epk[N_EDGES];               // packed edge: w15 | src17
__device__ int      g_bsum[NSCAN_BLOCKS];

// ---------------- CSR construction (4 kernels) ----------------
__global__ void hist_kernel(const int* __restrict__ dst) {
    int i = blockIdx.x * blockDim.x + threadIdx.x;
    if (i * 4 + 3 < N_EDGES) {
        int4 d = ((const int4*)dst)[i];
        atomicAdd(&g_deg[d.x], 1);
        atomicAdd(&g_deg[d.y], 1);
        atomicAdd(&g_deg[d.z], 1);
        atomicAdd(&g_deg[d.w], 1);
    } else {
        for (int e = i * 4; e < N_EDGES; e++) atomicAdd(&g_deg[dst[e]], 1);
    }
}

__global__ void scan_local_kernel() {
    __shared__ int s[1024];
    int tid = threadIdx.x;
    int i = blockIdx.x * 1024 + tid;
    int v = (i < N_NODES) ? g_deg[i] : 0;
    s[tid] = v;
    __syncthreads();
    #pragma unroll
    for (int d = 1; d < 1024; d <<= 1) {
        int t = (tid >= d) ? s[tid - d] : 0;
        __syncthreads();
        s[tid] += t;
        __syncthreads();
    }
    if (i < N_NODES) {
        g_off[i] = s[tid] - v;     // exclusive local
        g_deg[i] = 0;              // restore zero invariant for next launch
    }
    if (tid == 1023) g_bsum[blockIdx.x] = s[1023];
}

__global__ void scan_add_kernel() {
    __shared__ int red[32];
    int tid  = threadIdx.x;
    int lane = tid & 31;
    int wid  = tid >> 5;
    int pre = 0;
    for (int t = tid; t < blockIdx.x; t += 1024) pre += g_bsum[t];
    #pragma unroll
    for (int d = 16; d; d >>= 1) pre += __shfl_down_sync(0xffffffffu, pre, d);
    if (lane == 0) red[wid] = pre;
    __syncthreads();
    if (wid == 0) {
        int v = red[lane];
        #pragma unroll
        for (int d = 16; d; d >>= 1) v += __shfl_down_sync(0xffffffffu, v, d);
        if (lane == 0) red[0] = v;
    }
    __syncthreads();
    int base = red[0];

    int i = blockIdx.x * 1024 + tid;
    if (i < N_NODES) {
        int o = g_off[i] + base;
        g_off[i] = o;
        g_pos[i] = o;
    }
    if (blockIdx.x == 0 && tid == 0) g_off[N_NODES] = N_EDGES;
}

// scalar scatter: atomic-bound; vectorization measured neutral-to-negative.
__global__ void scatter_kernel(const int* __restrict__ src,
                               const int* __restrict__ dst,
                               const float* __restrict__ w) {
    int e = blockIdx.x * blockDim.x + threadIdx.x;
    if (e < N_EDGES) {
        int d = dst[e];
        int p = atomicAdd(&g_pos[d], 1);
        unsigned q = (unsigned)__float2int_rn(w[e] * WQ_SCALE);
        g_epk[p] = (q << 17) | (unsigned)src[e];
    }
}

// ---------------- fused MLP on tensor cores ----------------
// h = relu(x@W1+b1)@W2 + b2, bf16 hi/lo split (3 MMA passes), fp32 acc.
// Writes ONLY fp16 h (g_hh) — all prop iterations use fp16 h.
#define S1_STRIDE 40
#define S2_STRIDE 72
#define OFF_WREG  18432
#define SMEM_MLP_USHORT (18432 + 9216)
#define SMEM_MLP_BYTES  (SMEM_MLP_USHORT * 2)   // 55296 B

#define MMA_BF16(d, a, b0_, b1_)                                              \
    asm volatile("mma.sync.aligned.m16n8k16.row.col.f32.bf16.bf16.f32 "       \
                 "{%0,%1,%2,%3}, {%4,%5,%6,%7}, {%8,%9}, {%0,%1,%2,%3};"      \
                 : "+f"(d[0]), "+f"(d[1]), "+f"(d[2]), "+f"(d[3])             \
                 : "r"(a[0]), "r"(a[1]), "r"(a[2]), "r"(a[3]),                \
                   "r"(b0_), "r"(b1_))

__device__ __forceinline__ void bf16_split(float v, unsigned short& h,
                                           unsigned short& l) {
    __nv_bfloat16 hb = __float2bfloat16(v);
    float hf = __bfloat162float(hb);
    __nv_bfloat16 lb = __float2bfloat16(v - hf);
    h = __bfloat16_as_ushort(hb);
    l = __bfloat16_as_ushort(lb);
}

__global__ __launch_bounds__(256)
void mlp_tc_kernel(const float* __restrict__ A,
                   const float* __restrict__ W1, const float* __restrict__ b1,
                   const float* __restrict__ W2, const float* __restrict__ b2,
                   __half* __restrict__ Hh, int nrows) {
    extern __shared__ unsigned short sm[];
    unsigned short* xs_hi = sm;                         // 128*40
    unsigned short* xs_lo = sm + 128 * S1_STRIDE;
    unsigned short* wt_hi = sm + OFF_WREG;              // 64*40
    unsigned short* wt_lo = sm + OFF_WREG + 64 * S1_STRIDE;
    unsigned short* h1_hi = sm;                         // 128*72 (alias)
    unsigned short* h1_lo = sm + 128 * S2_STRIDE;
    unsigned short* w2_hi = sm + OFF_WREG;              // 64*72 (alias)
    unsigned short* w2_lo = sm + OFF_WREG + 64 * S2_STRIDE;

    const int tid  = threadIdx.x;
    const int wid  = tid >> 5;
    const int lane = tid & 31;
    const int g    = lane >> 2;
    const int tg2  = (lane & 3) * 2;
    const int warp_m = wid & 3;
    const int warp_n = wid >> 2;
    const int row0 = blockIdx.x * 128;

    float acc[2][4][4];
    #pragma unroll
    for (int mt = 0; mt < 2; mt++)
        #pragma unroll
        for (int nt = 0; nt < 4; nt++)
            #pragma unroll
            for (int c = 0; c < 4; c++) acc[mt][nt][c] = 0.f;

    // ================= stage 1: h1 = x @ W1 =================
    for (int ko = 0; ko < IN_F; ko += 32) {
        #pragma unroll
        for (int i = 0; i < 16; i++) {
            int idx = tid + i * 256;
            int r = idx >> 5;
            int c = idx & 31;
            int gr = row0 + r;
            int gk = ko + c;
            float v = (gr < nrows && gk < IN_F) ? __ldg(&A[(long)gr * IN_F + gk]) : 0.f;
            unsigned short hv, lv;
            bf16_split(v, hv, lv);
            xs_hi[r * S1_STRIDE + c] = hv;
            xs_lo[r * S1_STRIDE + c] = lv;
        }
        #pragma unroll
        for (int i = 0; i < 8; i++) {
            int idx = tid + i * 256;
            int k = idx >> 6;
            int n = idx & 63;
            int gk = ko + k;
            float v = (gk < IN_F) ? W1[gk * 64 + n] : 0.f;
            unsigned short hv, lv;
            bf16_split(v, hv, lv);
            wt_hi[n * S1_STRIDE + k] = hv;
            wt_lo[n * S1_STRIDE + k] = lv;
        }
        __syncthreads();

        #pragma unroll
        for (int ks = 0; ks < 2; ks++) {
            const int kk = ks * 16;
            unsigned ahi[2][4], alo[2][4];
            #pragma unroll
            for (int mt = 0; mt < 2; mt++) {
                int br = warp_m * 32 + mt * 16;
                const unsigned short* ph = &xs_hi[(br + g) * S1_STRIDE + kk + tg2];
                const unsigned short* pl = &xs_lo[(br + g) * S1_STRIDE + kk + tg2];
                ahi[mt][0] = *(const unsigned*)(ph);
                ahi[mt][1] = *(const unsigned*)(ph + 8 * S1_STRIDE);
                ahi[mt][2] = *(const unsigned*)(ph + 8);
                ahi[mt][3] = *(const unsigned*)(ph + 8 * S1_STRIDE + 8);
                alo[mt][0] = *(const unsigned*)(pl);
                alo[mt][1] = *(const unsigned*)(pl + 8 * S1_STRIDE);
                alo[mt][2] = *(const unsigned*)(pl + 8);
                alo[mt][3] = *(const unsigned*)(pl + 8 * S1_STRIDE + 8);
            }
            #pragma unroll
            for (int nt = 0; nt < 4; nt++) {
                int bn = warp_n * 32 + nt * 8 + g;
                const unsigned short* qh = &wt_hi[bn * S1_STRIDE + kk + tg2];
                const unsigned short* ql = &wt_lo[bn * S1_STRIDE + kk + tg2];
                unsigned bh0 = *(const unsigned*)(qh);
                unsigned bh1 = *(const unsigned*)(qh + 8);
                unsigned bl0 = *(const unsigned*)(ql);
                unsigned bl1 = *(const unsigned*)(ql + 8);
                #pragma unroll
                for (int mt = 0; mt < 2; mt++) {
                    MMA_BF16(acc[mt][nt], ahi[mt], bh0, bh1);
                    MMA_BF16(acc[mt][nt], ahi[mt], bl0, bl1);
                    MMA_BF16(acc[mt][nt], alo[mt], bh0, bh1);
                }
            }
        }
        __syncthreads();
    }

    // ============ inter-stage: bias1 + relu, h1 -> smem (bf16 hi/lo) ========
    #pragma unroll
    for (int mt = 0; mt < 2; mt++) {
        int r0 = warp_m * 32 + mt * 16 + g;
        int r1 = r0 + 8;
        #pragma unroll
        for (int nt = 0; nt < 4; nt++) {
            int col = warp_n * 32 + nt * 8 + tg2;
            float bb0 = b1[col], bb1 = b1[col + 1];
            float v0 = fmaxf(acc[mt][nt][0] + bb0, 0.f);
            float v1 = fmaxf(acc[mt][nt][1] + bb1, 0.f);
            float v2 = fmaxf(acc[mt][nt][2] + bb0, 0.f);
            float v3 = fmaxf(acc[mt][nt][3] + bb1, 0.f);
            unsigned short h0, l0, h1v, l1, h2, l2, h3, l3;
            bf16_split(v0, h0, l0); bf16_split(v1, h1v, l1);
            bf16_split(v2, h2, l2); bf16_split(v3, h3, l3);
            *(unsigned*)&h1_hi[r0 * S2_STRIDE + col] = (unsigned)h0 | ((unsigned)h1v << 16);
            *(unsigned*)&h1_lo[r0 * S2_STRIDE + col] = (unsigned)l0 | ((unsigned)l1 << 16);
            *(unsigned*)&h1_hi[r1 * S2_STRIDE + col] = (unsigned)h2 | ((unsigned)h3 << 16);
            *(unsigned*)&h1_lo[r1 * S2_STRIDE + col] = (unsigned)l2 | ((unsigned)l3 << 16);
            acc[mt][nt][0] = 0.f; acc[mt][nt][1] = 0.f;
            acc[mt][nt][2] = 0.f; acc[mt][nt][3] = 0.f;
        }
    }
    #pragma unroll
    for (int i = 0; i < 16; i++) {
        int idx = tid + i * 256;
        int k = idx >> 6;
        int n = idx & 63;
        float v = W2[k * 64 + n];
        unsigned short hv, lv;
        bf16_split(v, hv, lv);
        w2_hi[n * S2_STRIDE + k] = hv;
        w2_lo[n * S2_STRIDE + k] = lv;
    }
    __syncthreads();

    // ================= stage 2: h = h1 @ W2 (K=64) =================
    #pragma unroll
    for (int ks = 0; ks < 4; ks++) {
        const int kk = ks * 16;
        unsigned ahi[2][4], alo[2][4];
        #pragma unroll
        for (int mt = 0; mt < 2; mt++) {
            int br = warp_m * 32 + mt * 16;
            const unsigned short* ph = &h1_hi[(br + g) * S2_STRIDE + kk + tg2];
            const unsigned short* pl = &h1_lo[(br + g) * S2_STRIDE + kk + tg2];
            ahi[mt][0] = *(const unsigned*)(ph);
            ahi[mt][1] = *(const unsigned*)(ph + 8 * S2_STRIDE);
            ahi[mt][2] = *(const unsigned*)(ph + 8);
            ahi[mt][3] = *(const unsigned*)(ph + 8 * S2_STRIDE + 8);
            alo[mt][0] = *(const unsigned*)(pl);
            alo[mt][1] = *(const unsigned*)(pl + 8 * S2_STRIDE);
            alo[mt][2] = *(const unsigned*)(pl + 8);
            alo[mt][3] = *(const unsigned*)(pl + 8 * S2_STRIDE + 8);
        }
        #pragma unroll
        for (int nt = 0; nt < 4; nt++) {
            int bn = warp_n * 32 + nt * 8 + g;
            const unsigned short* qh = &w2_hi[bn * S2_STRIDE + kk + tg2];
            const unsigned short* ql = &w2_lo[bn * S2_STRIDE + kk + tg2];
            unsigned bh0 = *(const unsigned*)(qh);
            unsigned bh1 = *(const unsigned*)(qh + 8);
            unsigned bl0 = *(const unsigned*)(ql);
            unsigned bl1 = *(const unsigned*)(ql + 8);
            #pragma unroll
            for (int mt = 0; mt < 2; mt++) {
                MMA_BF16(acc[mt][nt], ahi[mt], bh0, bh1);
                MMA_BF16(acc[mt][nt], ahi[mt], bl0, bl1);
                MMA_BF16(acc[mt][nt], alo[mt], bh0, bh1);
            }
        }
    }

    // ============ epilogue: bias2, write fp16 h only ============
    #pragma unroll
    for (int mt = 0; mt < 2; mt++) {
        int r0 = row0 + warp_m * 32 + mt * 16 + g;
        int r1 = r0 + 8;
        #pragma unroll
        for (int nt = 0; nt < 4; nt++) {
            int col = warp_n * 32 + nt * 8 + tg2;
            float bb0 = b2[col], bb1 = b2[col + 1];
            if (r0 < nrows) {
                __half2 p = __floats2half2_rn(acc[mt][nt][0] + bb0,
                                              acc[mt][nt][1] + bb1);
                *(unsigned*)&Hh[(long)r0 * 64 + col] = *(unsigned*)&p;
            }
            if (r1 < nrows) {
                __half2 p = __floats2half2_rn(acc[mt][nt][2] + bb0,
                                              acc[mt][nt][3] + bb1);
                *(unsigned*)&Hh[(long)r1 * 64 + col] = *(unsigned*)&p;
            }
        }
    }
}

// ---------------- APPNP propagation (half-warp per edge, balanced tail) ----
#define PAIR_BODY(PJ) {                                                       \
    float wj = (float)((PJ) >> 17) * WQ_INV;                                  \
    uint2 v = *(const uint2*)(yin + ((long)((PJ) & 0x1FFFFu) << 6) + (hl << 2)); \
    float2 f0 = __half22float2(*(__half2*)&v.x);                              \
    float2 f1 = __half22float2(*(__half2*)&v.y);                              \
    a0 = fmaf(wj, f0.x, a0); a1 = fmaf(wj, f0.y, a1);                         \
    a2 = fmaf(wj, f1.x, a2); a3 = fmaf(wj, f1.y, a3); }

template <bool FINAL>
__global__ __launch_bounds__(256)
void prop_kernel(const __half* __restrict__ yin,
                 const uint2* __restrict__ hh,
                 uint2* __restrict__ yout, float4* __restrict__ fout,
                 float c1, float c2) {
    int gtid = blockIdx.x * blockDim.x + threadIdx.x;
    int node = gtid >> 5;
    int lane = threadIdx.x & 31;
    if (node >= N_NODES) return;
    const int hl = lane & 15;

    int beg = g_off[node];
    int end = g_off[node + 1];

    float a0 = 0.f, a1 = 0.f, a2 = 0.f, a3 = 0.f;
    int e = beg;
    for (; e + 32 <= end; e += 32) {
        unsigned pe = __ldg(&g_epk[e + lane]);
        #pragma unroll
        for (int j = 0; j < 16; j++) {
            unsigned pj = __shfl_sync(0xffffffffu, pe, j, 16);
            PAIR_BODY(pj)
        }
    }
    if (e < end) {
        int idx = e + lane;
        unsigned pe = (idx < end) ? __ldg(&g_epk[idx]) : 0u;
        int cnt  = end - e;                 // 1..31
        int jcnt = (cnt + 1) >> 1;
        int hoff = (lane & 16) ? jcnt : 0;
        for (int j = 0; j < jcnt; j++) {
            unsigned pj = __shfl_sync(0xffffffffu, pe, j + hoff, 32);
            PAIR_BODY(pj)
        }
    }
    a0 += __shfl_xor_sync(0xffffffffu, a0, 16);
    a1 += __shfl_xor_sync(0xffffffffu, a1, 16);
    a2 += __shfl_xor_sync(0xffffffffu, a2, 16);
    a3 += __shfl_xor_sync(0xffffffffu, a3, 16);

    if (lane < 16) {
        long oi = (long)node * 16 + hl;
        uint2 hv2 = hh[oi];
        float2 f0 = __half22float2(*(__half2*)&hv2.x);
        float2 f1 = __half22float2(*(__half2*)&hv2.y);
        float r0 = fmaf(c1, a0, c2 * f0.x);
        float r1 = fmaf(c1, a1, c2 * f0.y);
        float r2 = fmaf(c1, a2, c2 * f1.x);
        float r3 = fmaf(c1, a3, c2 * f1.y);
        if (FINAL) {
            fout[oi] = make_float4(r0, r1, r2, r3);
        } else {
            __half2 p0 = __floats2half2_rn(r0, r1);
            __half2 p1 = __floats2half2_rn(r2, r3);
            uint2 pv; pv.x = *(unsigned*)&p0; pv.y = *(unsigned*)&p1;
            yout[oi] = pv;
        }
    }
}

// ---------------- launch ----------------
extern "C" void kernel_launch(void* const* d_in, const int* in_sizes, int n_in,
                              void* d_out, int out_size) {
    const float* x    = (const float*)d_in[0];
    const int*   esrc = (const int*)d_in[1];
    const int*   edst = (const int*)d_in[2];
    const float* ew   = (const float*)d_in[3];
    const float* W1   = (const float*)d_in[4];
    const float* b1   = (const float*)d_in[5];
    const float* W2   = (const float*)d_in[6];
    const float* b2   = (const float*)d_in[7];
    float* out = (float*)d_out;

    static cudaStream_t s_side = nullptr;
    static cudaEvent_t  s_evFork = nullptr, s_evJoin = nullptr;
    if (!s_side) {
        cudaStreamCreateWithFlags(&s_side, cudaStreamNonBlocking);
        cudaEventCreateWithFlags(&s_evFork, cudaEventDisableTiming);
        cudaEventCreateWithFlags(&s_evJoin, cudaEventDisableTiming);
        cudaFuncSetAttribute(mlp_tc_kernel,
                             cudaFuncAttributeMaxDynamicSharedMemorySize,
                             SMEM_MLP_BYTES);
    }

    __half *hh_p, *ya_p, *yb_p;
    cudaGetSymbolAddress((void**)&hh_p, g_hh);
    cudaGetSymbolAddress((void**)&ya_p, g_ya);
    cudaGetSymbolAddress((void**)&yb_p, g_yb);

    // --- fork: CSR build on side stream, concurrent with fused MLP ---
    cudaEventRecord(s_evFork, 0);
    cudaStreamWaitEvent(s_side, s_evFork, 0);
    hist_kernel<<<(N_EDGES / 4 + 255) / 256, 256, 0, s_side>>>(edst);
    scan_local_kernel<<<NSCAN_BLOCKS, 1024, 0, s_side>>>();
    scan_add_kernel<<<NSCAN_BLOCKS, 1024, 0, s_side>>>();
    scatter_kernel<<<(N_EDGES + 255) / 256, 256, 0, s_side>>>(esrc, edst, ew);
    cudaEventRecord(s_evJoin, s_side);

    // --- fused MLP on main stream (writes fp16 h) ---
    int gblocks = (N_NODES + 127) / 128;
    mlp_tc_kernel<<<gblocks, 256, SMEM_MLP_BYTES>>>(x, W1, b1, W2, b2,
                                                    hh_p, N_NODES);

    // --- join, then K propagation steps ---
    cudaStreamWaitEvent(0, s_evJoin, 0);

    int pblocks = (N_NODES * 32 + 255) / 256;
    const __half* yin = hh_p;                 // y_0 = fp16(h)
    __half* ybufs[2] = { ya_p, yb_p };
    for (int k = 0; k < K_ITERS; k++) {
        if (k < K_ITERS - 1) {
            float c1 = (float)(0.9 * SCALE_S);
            float c2 = (float)(0.1 * pow(SCALE_S, (double)(k + 1)));
            __half* yo = ybufs[k & 1];
            prop_kernel<false><<<pblocks, 256>>>(yin, (const uint2*)hh_p,
                                                 (uint2*)yo, nullptr, c1, c2);
            yin = yo;
        } else {
            float c1 = (float)(0.9 * pow(1.0 / SCALE_S, (double)(K_ITERS - 1)));
            float c2 = 0.1f;
            prop_kernel<true><<<pblocks, 256>>>(yin, (const uint2*)hh_p,
                                                nullptr, (float4*)out, c1, c2);
        }
    }
}

// round 17
// speedup vs baseline: 1.0140x; 1.0001x over previous
#include <cuda_runtime.h>
#include <cuda_bf16.h>
#include <cuda_fp16.h>
#include <math.h>

// ---------------- problem constants ----------------
#define N_NODES 100000
#define N_EDGES 3200000
#define IN_F    500
#define HID     64
#define OUT_F   64
#define ALPHA   0.1f
#define K_ITERS 10

#define NSCAN_BLOCKS ((N_NODES + 1023) / 1024)   // 98
#define SCALE_S 0.0625                            // 1/16 per-iteration z scaling
#define WQ_SCALE 32767.0f
#define WQ_INV   (1.0f / 32767.0f)

typedef unsigned long long u64;

// ---------------- static device scratch ----------------
__device__ __half   g_hh[N_NODES * OUT_F];        // fp16 h (= y_0, alpha term)
__device__ __half   g_ya[N_NODES * OUT_F];        // fp16 iterate ping
__device__ __half   g_yb[N_NODES * OUT_F];        // fp16 iterate pong
__device__ int      g_deg[N_NODES];               // ALWAYS zero at launch entry
__device__ int      g_off[N_NODES + 1];
__device__ int      g_pos[N_NODES];
__device__ unsigned g_epk[N_EDGES];               // packed edge: w15 | src17
__device__ int      g_bsum[NSCAN_BLOCKS];

// ---------------- CSR construction (4 kernels) ----------------
__global__ void hist_kernel(const int* __restrict__ dst) {
    int i = blockIdx.x * blockDim.x + threadIdx.x;
    if (i * 4 + 3 < N_EDGES) {
        int4 d = ((const int4*)dst)[i];
        atomicAdd(&g_deg[d.x], 1);
        atomicAdd(&g_deg[d.y], 1);
        atomicAdd(&g_deg[d.z], 1);
        atomicAdd(&g_deg[d.w], 1);
    } else {
        for (int e = i * 4; e < N_EDGES; e++) atomicAdd(&g_deg[dst[e]], 1);
    }
}

__global__ void scan_local_kernel() {
    __shared__ int s[1024];
    int tid = threadIdx.x;
    int i = blockIdx.x * 1024 + tid;
    int v = (i < N_NODES) ? g_deg[i] : 0;
    s[tid] = v;
    __syncthreads();
    #pragma unroll
    for (int d = 1; d < 1024; d <<= 1) {
        int t = (tid >= d) ? s[tid - d] : 0;
        __syncthreads();
        s[tid] += t;
        __syncthreads();
    }
    if (i < N_NODES) {
        g_off[i] = s[tid] - v;     // exclusive local
        g_deg[i] = 0;              // restore zero invariant for next launch
    }
    if (tid == 1023) g_bsum[blockIdx.x] = s[1023];
}

__global__ void scan_add_kernel() {
    __shared__ int red[32];
    int tid  = threadIdx.x;
    int lane = tid & 31;
    int wid  = tid >> 5;
    int pre = 0;
    for (int t = tid; t < blockIdx.x; t += 1024) pre += g_bsum[t];
    #pragma unroll
    for (int d = 16; d; d >>= 1) pre += __shfl_down_sync(0xffffffffu, pre, d);
    if (lane == 0) red[wid] = pre;
    __syncthreads();
    if (wid == 0) {
        int v = red[lane];
        #pragma unroll
        for (int d = 16; d; d >>= 1) v += __shfl_down_sync(0xffffffffu, v, d);
        if (lane == 0) red[0] = v;
    }
    __syncthreads();
    int base = red[0];

    int i = blockIdx.x * 1024 + tid;
    if (i < N_NODES) {
        int o = g_off[i] + base;
        g_off[i] = o;
        g_pos[i] = o;
    }
    if (blockIdx.x == 0 && tid == 0) g_off[N_NODES] = N_EDGES;
}

// scalar scatter: atomic/store-bound; vectorization measured neutral.
__global__ void scatter_kernel(const int* __restrict__ src,
                               const int* __restrict__ dst,
                               const float* __restrict__ w) {
    int e = blockIdx.x * blockDim.x + threadIdx.x;
    if (e < N_EDGES) {
        int d = dst[e];
        int p = atomicAdd(&g_pos[d], 1);
        unsigned q = (unsigned)__float2int_rn(w[e] * WQ_SCALE);
        g_epk[p] = (q << 17) | (unsigned)src[e];
    }
}

// ---------------- fused MLP on tensor cores ----------------
// h = relu(x@W1+b1)@W2 + b2, bf16 hi/lo split (3 MMA passes), fp32 acc.
// Writes ONLY fp16 h (g_hh) — all prop iterations use fp16 h.
#define S1_STRIDE 40
#define S2_STRIDE 72
#define OFF_WREG  18432
#define SMEM_MLP_USHORT (18432 + 9216)
#define SMEM_MLP_BYTES  (SMEM_MLP_USHORT * 2)   // 55296 B

#define MMA_BF16(d, a, b0_, b1_)                                              \
    asm volatile("mma.sync.aligned.m16n8k16.row.col.f32.bf16.bf16.f32 "       \
                 "{%0,%1,%2,%3}, {%4,%5,%6,%7}, {%8,%9}, {%0,%1,%2,%3};"      \
                 : "+f"(d[0]), "+f"(d[1]), "+f"(d[2]), "+f"(d[3])             \
                 : "r"(a[0]), "r"(a[1]), "r"(a[2]), "r"(a[3]),                \
                   "r"(b0_), "r"(b1_))

__device__ __forceinline__ void bf16_split(float v, unsigned short& h,
                                           unsigned short& l) {
    __nv_bfloat16 hb = __float2bfloat16(v);
    float hf = __bfloat162float(hb);
    __nv_bfloat16 lb = __float2bfloat16(v - hf);
    h = __bfloat16_as_ushort(hb);
    l = __bfloat16_as_ushort(lb);
}

__global__ __launch_bounds__(256)
void mlp_tc_kernel(const float* __restrict__ A,
                   const float* __restrict__ W1, const float* __restrict__ b1,
                   const float* __restrict__ W2, const float* __restrict__ b2,
                   __half* __restrict__ Hh, int nrows) {
    extern __shared__ unsigned short sm[];
    unsigned short* xs_hi = sm;                         // 128*40
    unsigned short* xs_lo = sm + 128 * S1_STRIDE;
    unsigned short* wt_hi = sm + OFF_WREG;              // 64*40
    unsigned short* wt_lo = sm + OFF_WREG + 64 * S1_STRIDE;
    unsigned short* h1_hi = sm;                         // 128*72 (alias)
    unsigned short* h1_lo = sm + 128 * S2_STRIDE;
    unsigned short* w2_hi = sm + OFF_WREG;              // 64*72 (alias)
    unsigned short* w2_lo = sm + OFF_WREG + 64 * S2_STRIDE;

    const int tid  = threadIdx.x;
    const int wid  = tid >> 5;
    const int lane = tid & 31;
    const int g    = lane >> 2;
    const int tg2  = (lane & 3) * 2;
    const int warp_m = wid & 3;
    const int warp_n = wid >> 2;
    const int row0 = blockIdx.x * 128;

    float acc[2][4][4];
    #pragma unroll
    for (int mt = 0; mt < 2; mt++)
        #pragma unroll
        for (int nt = 0; nt < 4; nt++)
            #pragma unroll
            for (int c = 0; c < 4; c++) acc[mt][nt][c] = 0.f;

    // ================= stage 1: h1 = x @ W1 =================
    for (int ko = 0; ko < IN_F; ko += 32) {
        #pragma unroll
        for (int i = 0; i < 16; i++) {
            int idx = tid + i * 256;
            int r = idx >> 5;
            int c = idx & 31;
            int gr = row0 + r;
            int gk = ko + c;
            float v = (gr < nrows && gk < IN_F) ? __ldg(&A[(long)gr * IN_F + gk]) : 0.f;
            unsigned short hv, lv;
            bf16_split(v, hv, lv);
            xs_hi[r * S1_STRIDE + c] = hv;
            xs_lo[r * S1_STRIDE + c] = lv;
        }
        #pragma unroll
        for (int i = 0; i < 8; i++) {
            int idx = tid + i * 256;
            int k = idx >> 6;
            int n = idx & 63;
            int gk = ko + k;
            float v = (gk < IN_F) ? W1[gk * 64 + n] : 0.f;
            unsigned short hv, lv;
            bf16_split(v, hv, lv);
            wt_hi[n * S1_STRIDE + k] = hv;
            wt_lo[n * S1_STRIDE + k] = lv;
        }
        __syncthreads();

        #pragma unroll
        for (int ks = 0; ks < 2; ks++) {
            const int kk = ks * 16;
            unsigned ahi[2][4], alo[2][4];
            #pragma unroll
            for (int mt = 0; mt < 2; mt++) {
                int br = warp_m * 32 + mt * 16;
                const unsigned short* ph = &xs_hi[(br + g) * S1_STRIDE + kk + tg2];
                const unsigned short* pl = &xs_lo[(br + g) * S1_STRIDE + kk + tg2];
                ahi[mt][0] = *(const unsigned*)(ph);
                ahi[mt][1] = *(const unsigned*)(ph + 8 * S1_STRIDE);
                ahi[mt][2] = *(const unsigned*)(ph + 8);
                ahi[mt][3] = *(const unsigned*)(ph + 8 * S1_STRIDE + 8);
                alo[mt][0] = *(const unsigned*)(pl);
                alo[mt][1] = *(const unsigned*)(pl + 8 * S1_STRIDE);
                alo[mt][2] = *(const unsigned*)(pl + 8);
                alo[mt][3] = *(const unsigned*)(pl + 8 * S1_STRIDE + 8);
            }
            #pragma unroll
            for (int nt = 0; nt < 4; nt++) {
                int bn = warp_n * 32 + nt * 8 + g;
                const unsigned short* qh = &wt_hi[bn * S1_STRIDE + kk + tg2];
                const unsigned short* ql = &wt_lo[bn * S1_STRIDE + kk + tg2];
                unsigned bh0 = *(const unsigned*)(qh);
                unsigned bh1 = *(const unsigned*)(qh + 8);
                unsigned bl0 = *(const unsigned*)(ql);
                unsigned bl1 = *(const unsigned*)(ql + 8);
                #pragma unroll
                for (int mt = 0; mt < 2; mt++) {
                    MMA_BF16(acc[mt][nt], ahi[mt], bh0, bh1);
                    MMA_BF16(acc[mt][nt], ahi[mt], bl0, bl1);
                    MMA_BF16(acc[mt][nt], alo[mt], bh0, bh1);
                }
            }
        }
        __syncthreads();
    }

    // ============ inter-stage: bias1 + relu, h1 -> smem (bf16 hi/lo) ========
    #pragma unroll
    for (int mt = 0; mt < 2; mt++) {
        int r0 = warp_m * 32 + mt * 16 + g;
        int r1 = r0 + 8;
        #pragma unroll
        for (int nt = 0; nt < 4; nt++) {
            int col = warp_n * 32 + nt * 8 + tg2;
            float bb0 = b1[col], bb1 = b1[col + 1];
            float v0 = fmaxf(acc[mt][nt][0] + bb0, 0.f);
            float v1 = fmaxf(acc[mt][nt][1] + bb1, 0.f);
            float v2 = fmaxf(acc[mt][nt][2] + bb0, 0.f);
            float v3 = fmaxf(acc[mt][nt][3] + bb1, 0.f);
            unsigned short h0, l0, h1v, l1, h2, l2, h3, l3;
            bf16_split(v0, h0, l0); bf16_split(v1, h1v, l1);
            bf16_split(v2, h2, l2); bf16_split(v3, h3, l3);
            *(unsigned*)&h1_hi[r0 * S2_STRIDE + col] = (unsigned)h0 | ((unsigned)h1v << 16);
            *(unsigned*)&h1_lo[r0 * S2_STRIDE + col] = (unsigned)l0 | ((unsigned)l1 << 16);
            *(unsigned*)&h1_hi[r1 * S2_STRIDE + col] = (unsigned)h2 | ((unsigned)h3 << 16);
            *(unsigned*)&h1_lo[r1 * S2_STRIDE + col] = (unsigned)l2 | ((unsigned)l3 << 16);
            acc[mt][nt][0] = 0.f; acc[mt][nt][1] = 0.f;
            acc[mt][nt][2] = 0.f; acc[mt][nt][3] = 0.f;
        }
    }
    #pragma unroll
    for (int i = 0; i < 16; i++) {
        int idx = tid + i * 256;
        int k = idx >> 6;
        int n = idx & 63;
        float v = W2[k * 64 + n];
        unsigned short hv, lv;
        bf16_split(v, hv, lv);
        w2_hi[n * S2_STRIDE + k] = hv;
        w2_lo[n * S2_STRIDE + k] = lv;
    }
    __syncthreads();

    // ================= stage 2: h = h1 @ W2 (K=64) =================
    #pragma unroll
    for (int ks = 0; ks < 4; ks++) {
        const int kk = ks * 16;
        unsigned ahi[2][4], alo[2][4];
        #pragma unroll
        for (int mt = 0; mt < 2; mt++) {
            int br = warp_m * 32 + mt * 16;
            const unsigned short* ph = &h1_hi[(br + g) * S2_STRIDE + kk + tg2];
            const unsigned short* pl = &h1_lo[(br + g) * S2_STRIDE + kk + tg2];
            ahi[mt][0] = *(const unsigned*)(ph);
            ahi[mt][1] = *(const unsigned*)(ph + 8 * S2_STRIDE);
            ahi[mt][2] = *(const unsigned*)(ph + 8);
            ahi[mt][3] = *(const unsigned*)(ph + 8 * S2_STRIDE + 8);
            alo[mt][0] = *(const unsigned*)(pl);
            alo[mt][1] = *(const unsigned*)(pl + 8 * S2_STRIDE);
            alo[mt][2] = *(const unsigned*)(pl + 8);
            alo[mt][3] = *(const unsigned*)(pl + 8 * S2_STRIDE + 8);
        }
        #pragma unroll
        for (int nt = 0; nt < 4; nt++) {
            int bn = warp_n * 32 + nt * 8 + g;
            const unsigned short* qh = &w2_hi[bn * S2_STRIDE + kk + tg2];
            const unsigned short* ql = &w2_lo[bn * S2_STRIDE + kk + tg2];
            unsigned bh0 = *(const unsigned*)(qh);
            unsigned bh1 = *(const unsigned*)(qh + 8);
            unsigned bl0 = *(const unsigned*)(ql);
            unsigned bl1 = *(const unsigned*)(ql + 8);
            #pragma unroll
            for (int mt = 0; mt < 2; mt++) {
                MMA_BF16(acc[mt][nt], ahi[mt], bh0, bh1);
                MMA_BF16(acc[mt][nt], ahi[mt], bl0, bl1);
                MMA_BF16(acc[mt][nt], alo[mt], bh0, bh1);
            }
        }
    }

    // ============ epilogue: bias2, write fp16 h only ============
    #pragma unroll
    for (int mt = 0; mt < 2; mt++) {
        int r0 = row0 + warp_m * 32 + mt * 16 + g;
        int r1 = r0 + 8;
        #pragma unroll
        for (int nt = 0; nt < 4; nt++) {
            int col = warp_n * 32 + nt * 8 + tg2;
            float bb0 = b2[col], bb1 = b2[col + 1];
            if (r0 < nrows) {
                __half2 p = __floats2half2_rn(acc[mt][nt][0] + bb0,
                                              acc[mt][nt][1] + bb1);
                *(unsigned*)&Hh[(long)r0 * 64 + col] = *(unsigned*)&p;
            }
            if (r1 < nrows) {
                __half2 p = __floats2half2_rn(acc[mt][nt][2] + bb0,
                                              acc[mt][nt][3] + bb1);
                *(unsigned*)&Hh[(long)r1 * 64 + col] = *(unsigned*)&p;
            }
        }
    }
}

// ---------------- APPNP propagation (half-warp per edge, balanced tail) ----
#define PAIR_BODY(PJ) {                                                       \
    float wj = (float)((PJ) >> 17) * WQ_INV;                                  \
    uint2 v = *(const uint2*)(yin + ((long)((PJ) & 0x1FFFFu) << 6) + (hl << 2)); \
    float2 f0 = __half22float2(*(__half2*)&v.x);                              \
    float2 f1 = __half22float2(*(__half2*)&v.y);                              \
    a0 = fmaf(wj, f0.x, a0); a1 = fmaf(wj, f0.y, a1);                         \
    a2 = fmaf(wj, f1.x, a2); a3 = fmaf(wj, f1.y, a3); }

template <bool FINAL>
__global__ __launch_bounds__(256)
void prop_kernel(const __half* __restrict__ yin,
                 const uint2* __restrict__ hh,
                 uint2* __restrict__ yout, float4* __restrict__ fout,
                 float c1, float c2) {
    int gtid = blockIdx.x * blockDim.x + threadIdx.x;
    int node = gtid >> 5;
    int lane = threadIdx.x & 31;
    if (node >= N_NODES) return;
    const int hl = lane & 15;

    int beg = g_off[node];
    int end = g_off[node + 1];

    float a0 = 0.f, a1 = 0.f, a2 = 0.f, a3 = 0.f;
    int e = beg;
    for (; e + 32 <= end; e += 32) {
        unsigned pe = __ldg(&g_epk[e + lane]);
        #pragma unroll
        for (int j = 0; j < 16; j++) {
            unsigned pj = __shfl_sync(0xffffffffu, pe, j, 16);
            PAIR_BODY(pj)
        }
    }
    if (e < end) {
        int idx = e + lane;
        unsigned pe = (idx < end) ? __ldg(&g_epk[idx]) : 0u;
        int cnt  = end - e;                 // 1..31
        int jcnt = (cnt + 1) >> 1;
        int hoff = (lane & 16) ? jcnt : 0;
        for (int j = 0; j < jcnt; j++) {
            unsigned pj = __shfl_sync(0xffffffffu, pe, j + hoff, 32);
            PAIR_BODY(pj)
        }
    }

    // hoist alpha-term load before the reduction: both halves load the same
    // address (L1 broadcast), overlapping its latency with the shuffles.
    long oi = (long)node * 16 + hl;
    uint2 hv2 = __ldg(&hh[oi]);

    a0 += __shfl_xor_sync(0xffffffffu, a0, 16);
    a1 += __shfl_xor_sync(0xffffffffu, a1, 16);
    a2 += __shfl_xor_sync(0xffffffffu, a2, 16);
    a3 += __shfl_xor_sync(0xffffffffu, a3, 16);

    if (lane < 16) {
        float2 f0 = __half22float2(*(__half2*)&hv2.x);
        float2 f1 = __half22float2(*(__half2*)&hv2.y);
        float r0 = fmaf(c1, a0, c2 * f0.x);
        float r1 = fmaf(c1, a1, c2 * f0.y);
        float r2 = fmaf(c1, a2, c2 * f1.x);
        float r3 = fmaf(c1, a3, c2 * f1.y);
        if (FINAL) {
            fout[oi] = make_float4(r0, r1, r2, r3);
        } else {
            __half2 p0 = __floats2half2_rn(r0, r1);
            __half2 p1 = __floats2half2_rn(r2, r3);
            uint2 pv; pv.x = *(unsigned*)&p0; pv.y = *(unsigned*)&p1;
            yout[oi] = pv;
        }
    }
}

// ---------------- launch ----------------
extern "C" void kernel_launch(void* const* d_in, const int* in_sizes, int n_in,
                              void* d_out, int out_size) {
    const float* x    = (const float*)d_in[0];
    const int*   esrc = (const int*)d_in[1];
    const int*   edst = (const int*)d_in[2];
    const float* ew   = (const float*)d_in[3];
    const float* W1   = (const float*)d_in[4];
    const float* b1   = (const float*)d_in[5];
    const float* W2   = (const float*)d_in[6];
    const float* b2   = (const float*)d_in[7];
    float* out = (float*)d_out;

    static cudaStream_t s_side = nullptr;
    static cudaEvent_t  s_evFork = nullptr, s_evJoin = nullptr;
    if (!s_side) {
        cudaStreamCreateWithFlags(&s_side, cudaStreamNonBlocking);
        cudaEventCreateWithFlags(&s_evFork, cudaEventDisableTiming);
        cudaEventCreateWithFlags(&s_evJoin, cudaEventDisableTiming);
        cudaFuncSetAttribute(mlp_tc_kernel,
                             cudaFuncAttributeMaxDynamicSharedMemorySize,
                             SMEM_MLP_BYTES);
    }

    __half *hh_p, *ya_p, *yb_p;
    cudaGetSymbolAddress((void**)&hh_p, g_hh);
    cudaGetSymbolAddress((void**)&ya_p, g_ya);
    cudaGetSymbolAddress((void**)&yb_p, g_yb);

    // --- fork: CSR build on side stream, concurrent with fused MLP ---
    cudaEventRecord(s_evFork, 0);
    cudaStreamWaitEvent(s_side, s_evFork, 0);
    hist_kernel<<<(N_EDGES / 4 + 255) / 256, 256, 0, s_side>>>(edst);
    scan_local_kernel<<<NSCAN_BLOCKS, 1024, 0, s_side>>>();
    scan_add_kernel<<<NSCAN_BLOCKS, 1024, 0, s_side>>>();
    scatter_kernel<<<(N_EDGES + 255) / 256, 256, 0, s_side>>>(esrc, edst, ew);
    cudaEventRecord(s_evJoin, s_side);

    // --- fused MLP on main stream (writes fp16 h) ---
    int gblocks = (N_NODES + 127) / 128;
    mlp_tc_kernel<<<gblocks, 256, SMEM_MLP_BYTES>>>(x, W1, b1, W2, b2,
                                                    hh_p, N_NODES);

    // --- join, then K propagation steps ---
    cudaStreamWaitEvent(0, s_evJoin, 0);

    int pblocks = (N_NODES * 32 + 255) / 256;
    const __half* yin = hh_p;                 // y_0 = fp16(h)
    __half* ybufs[2] = { ya_p, yb_p };
    for (int k = 0; k < K_ITERS; k++) {
        if (k < K_ITERS - 1) {
            float c1 = (float)(0.9 * SCALE_S);
            float c2 = (float)(0.1 * pow(SCALE_S, (double)(k + 1)));
            __half* yo = ybufs[k & 1];
            prop_kernel<false><<<pblocks, 256>>>(yin, (const uint2*)hh_p,
                                                 (uint2*)yo, nullptr, c1, c2);
            yin = yo;
        } else {
            float c1 = (float)(0.9 * pow(1.0 / SCALE_S, (double)(K_ITERS - 1)));
            float c2 = 0.1f;
            prop_kernel<true><<<pblocks, 256>>>(yin, (const uint2*)hh_p,
                                                nullptr, (float4*)out, c1, c2);
        }
    }
}